// round 3
// baseline (speedup 1.0000x reference)
#include <cuda_runtime.h>
#include <cstdint>
#include <cstddef>

#define TOKENS 16384
#define HIDDEN 2048
#define NEXP   64
#define BM     128
#define BK     16
#define NTH    256
#define NIT    (HIDDEN / BK)

#define OFF_GATES (TOKENS * 2)
#define OFF_SEL   (OFF_GATES + TOKENS * NEXP)
#define OFF_Z     (OFF_SEL + TOKENS * 2)

__device__ float g_logits[(size_t)TOKENS * NEXP];
__device__ float g_z[TOKENS];

__device__ __forceinline__ unsigned long long ffma2(unsigned long long a,
                                                    unsigned long long b,
                                                    unsigned long long c) {
    unsigned long long d;
    asm("fma.rn.f32x2 %0, %1, %2, %3;" : "=l"(d) : "l"(a), "l"(b), "l"(c));
    return d;
}
__device__ __forceinline__ unsigned long long packdup(float v) {
    unsigned long long d;
    asm("mov.b64 %0, {%1, %1};" : "=l"(d) : "f"(v));
    return d;
}
__device__ __forceinline__ float2 unpack2(unsigned long long v) {
    float2 f;
    asm("mov.b64 {%0, %1}, %2;" : "=f"(f.x), "=f"(f.y) : "l"(v));
    return f;
}

// ---------------------------------------------------------------------------
// Kernel 1: logits = x @ w^T  (fp32, f32x2-packed FFMA, double-buffered smem)
// grid = TOKENS/BM = 128 CTAs, 256 threads.
// Thread t: token = t&127, experts [(t>>7)*32, +32). 32 fp32 accs as 16 f32x2.
// ---------------------------------------------------------------------------
__global__ __launch_bounds__(NTH, 1) void gemm_kernel(const float* __restrict__ x,
                                                      const float* __restrict__ w) {
    __shared__ __align__(16) float As[2][BM][BK + 4];  // stride 20 floats (80B, 16B-mult)
    __shared__ __align__(16) float Bs[2][BK][NEXP];    // transposed w tile: [k][expert]

    const int t   = threadIdx.x;
    const int m0  = blockIdx.x * BM;
    const int tok = t & (BM - 1);
    const int e0  = (t >> 7) << 5;  // 0 or 32

    const int a_kq  = t & 3;        // float4 col within BK
    const int a_row = t >> 2;       // rows a_row and a_row+64
    const int b_er  = t & 63;       // expert row of w
    const int b_kq  = t >> 6;       // float4 col within BK

    const float* xg = x + (size_t)(m0 + a_row) * HIDDEN + a_kq * 4;
    const float* wg = w + (size_t)b_er * HIDDEN + b_kq * 4;

    float4 pa0, pa1, pb;
    unsigned long long acc[16];
#pragma unroll
    for (int i = 0; i < 16; i++) acc[i] = 0ULL;

    // initial tile -> buf 0
    pa0 = *(const float4*)(xg);
    pa1 = *(const float4*)(xg + (size_t)64 * HIDDEN);
    pb  = *(const float4*)(wg);
    *(float4*)&As[0][a_row][a_kq * 4]      = pa0;
    *(float4*)&As[0][a_row + 64][a_kq * 4] = pa1;
    Bs[0][b_kq * 4 + 0][b_er] = pb.x;
    Bs[0][b_kq * 4 + 1][b_er] = pb.y;
    Bs[0][b_kq * 4 + 2][b_er] = pb.z;
    Bs[0][b_kq * 4 + 3][b_er] = pb.w;
    __syncthreads();

    int buf = 0;
    for (int it = 0; it < NIT; it++) {
        if (it + 1 < NIT) {
            const int kc = (it + 1) * BK;
            pa0 = *(const float4*)(xg + kc);
            pa1 = *(const float4*)(xg + (size_t)64 * HIDDEN + kc);
            pb  = *(const float4*)(wg + kc);
        }
#pragma unroll
        for (int k = 0; k < BK; k++) {
            const unsigned long long a2 = packdup(As[buf][tok][k]);
            const ulonglong2* bp = (const ulonglong2*)&Bs[buf][k][e0];
#pragma unroll
            for (int q = 0; q < 8; q++) {
                ulonglong2 b = bp[q];
                acc[2 * q]     = ffma2(a2, b.x, acc[2 * q]);
                acc[2 * q + 1] = ffma2(a2, b.y, acc[2 * q + 1]);
            }
        }
        if (it + 1 < NIT) {
            __syncthreads();
            const int nb = buf ^ 1;
            *(float4*)&As[nb][a_row][a_kq * 4]      = pa0;
            *(float4*)&As[nb][a_row + 64][a_kq * 4] = pa1;
            Bs[nb][b_kq * 4 + 0][b_er] = pb.x;
            Bs[nb][b_kq * 4 + 1][b_er] = pb.y;
            Bs[nb][b_kq * 4 + 2][b_er] = pb.z;
            Bs[nb][b_kq * 4 + 3][b_er] = pb.w;
            __syncthreads();
            buf = nb;
        }
    }

    float* dst = g_logits + (size_t)(m0 + tok) * NEXP + e0;
#pragma unroll
    for (int q = 0; q < 8; q++) {
        float2 lo = unpack2(acc[2 * q]);
        float2 hi = unpack2(acc[2 * q + 1]);
        *(float4*)(dst + q * 4) = make_float4(lo.x, lo.y, hi.x, hi.y);
    }
}

// ---------------------------------------------------------------------------
// Kernel 2: sparse-mixer routing. One warp per token; lane owns experts l, l+32.
// ---------------------------------------------------------------------------
__device__ __forceinline__ void warp_argmax(float& v, int& i) {
#pragma unroll
    for (int m = 16; m; m >>= 1) {
        float ov = __shfl_xor_sync(0xffffffffu, v, m);
        int   oi = __shfl_xor_sync(0xffffffffu, i, m);
        if (ov > v || (ov == v && oi < i)) { v = ov; i = oi; }
    }
}
__device__ __forceinline__ float warp_sum(float s) {
#pragma unroll
    for (int m = 16; m; m >>= 1) s += __shfl_xor_sync(0xffffffffu, s, m);
    return s;
}

__global__ void route_kernel(float* __restrict__ out) {
    const int warp = (blockIdx.x * blockDim.x + threadIdx.x) >> 5;
    const int lane = threadIdx.x & 31;
    const float NINF = __int_as_float(0xff800000);

    const float* row = g_logits + (size_t)warp * NEXP;
    const float v0 = row[lane];
    const float v1 = row[lane + 32];
    const int   i0 = lane, i1 = lane + 32;

    // ---- pass 1: top-1 ----
    float bv; int bi;
    if (v0 >= v1) { bv = v0; bi = i0; } else { bv = v1; bi = i1; }
    warp_argmax(bv, bi);
    const float mx1 = bv;
    const int   s1  = bi;

    const float ea0 = expf(v0 - mx1);
    const float ea1 = expf(v1 - mx1);
    const float sAll = warp_sum(ea0 + ea1);

    // mask: (mx - scores)/max(|scores|, mx) > 2*jitter_eps  (= 0.02)
    const float f0 = fmaxf(fabsf(v0), mx1);
    const float f1 = fmaxf(fabsf(v1), mx1);
    const bool mask10 = ((mx1 - v0) / f0) > 0.02f;
    const bool mask11 = ((mx1 - v1) / f1) > 0.02f;
    const float sum1 = warp_sum((mask10 ? 0.f : ea0) + (mask11 ? 0.f : ea1));
    const float mult1 = 1.0f / sum1;   // gates[sel] = exp(0)/sum_masked

    // ---- pass 2: mask out s1, repeat ----
    const float w0 = (i0 == s1) ? NINF : v0;
    const float w1 = (i1 == s1) ? NINF : v1;
    float bv2; int bi2;
    if (w0 >= w1) { bv2 = w0; bi2 = i0; } else { bv2 = w1; bi2 = i1; }
    warp_argmax(bv2, bi2);
    const float mx2 = bv2;
    const int   s2  = bi2;

    const float g0 = fmaxf(fabsf(v0), mx2);
    const float g1 = fmaxf(fabsf(v1), mx2);
    const bool mask20 = ((mx2 - v0) / g0) > 0.02f;
    const bool mask21 = ((mx2 - v1) / g1) > 0.02f;
    const float e20 = (i0 == s1 || mask20) ? 0.f : expf(v0 - mx2);
    const float e21 = (i1 == s1 || mask21) ? 0.f : expf(v1 - mx2);
    const float sum2 = warp_sum(e20 + e21);
    const float mult2 = 1.0f / sum2;

    // ---- outputs ----
    const float invAll = 1.0f / sAll;
    out[OFF_GATES + (size_t)warp * NEXP + lane]      = ea0 * invAll;
    out[OFF_GATES + (size_t)warp * NEXP + lane + 32] = ea1 * invAll;
    if (lane == 0) {
        out[warp * 2 + 0] = mult1;
        out[warp * 2 + 1] = mult2;
        out[OFF_SEL + warp * 2 + 0] = (float)s1;
        out[OFF_SEL + warp * 2 + 1] = (float)s2;
        const float lse = mx1 + logf(sAll);
        g_z[warp] = lse * lse;
    }
}

// ---------------------------------------------------------------------------
// Kernel 3: deterministic z-loss reduction (fixed order, single CTA)
// ---------------------------------------------------------------------------
__global__ void zred_kernel(float* __restrict__ out) {
    __shared__ float red[1024];
    const int t = threadIdx.x;
    float s = 0.f;
#pragma unroll
    for (int i = 0; i < TOKENS / 1024; i++) s += g_z[t + i * 1024];
    red[t] = s;
    __syncthreads();
    for (int stride = 512; stride > 0; stride >>= 1) {
        if (t < stride) red[t] += red[t + stride];
        __syncthreads();
    }
    if (t == 0) out[OFF_Z] = 0.001f * (red[0] / (float)TOKENS);
}

extern "C" void kernel_launch(void* const* d_in, const int* in_sizes, int n_in,
                              void* d_out, int out_size) {
    const float* x = (const float*)d_in[0];
    const float* w = (const float*)d_in[1];
    float* out = (float*)d_out;

    gemm_kernel<<<TOKENS / BM, NTH>>>(x, w);
    route_kernel<<<(TOKENS * 32) / 256, 256>>>(out);
    zred_kernel<<<1, 1024>>>(out);
}